// round 5
// baseline (speedup 1.0000x reference)
#include <cuda_runtime.h>
#include <cuda_bf16.h>
#include <math.h>
#include <stdint.h>

#define B_   32
#define TT_  799
#define T1_  1599
#define W1_  39
#define W2_  19
#define D0_  608
#define U_   512
#define G4_  2048
#define MT_  (B_ * TT_)            // 25568

#define X_SZ   ((size_t)MT_ * 1024)
#define OFF_M  (X_SZ)
#define OFF_H  (X_SZ + MT_)
#define OFF_C  (OFF_H + (size_t)B_ * 512)
#define TOTAL_ (OFF_C + (size_t)B_ * 512)

// ----------------------------- scratch --------------------------------------
__device__ float g_x1[(size_t)B_ * T1_ * W1_ * 32];
__device__ float g_x2[(size_t)MT_ * D0_];
__device__ float g_zf[(size_t)MT_ * G4_];
__device__ float g_zb[(size_t)MT_ * G4_];
__device__ float g_xcat[(size_t)MT_ * 1024];
__device__ float g_xp0[(size_t)MT_ * 1024];
__device__ float g_xp1[(size_t)MT_ * 1024];
__device__ float g_mask[MT_];
__device__ float g_H[2][2][U_ * B_];     // [dir][parity][k*32+b]
__device__ float g_S[4][U_ * B_];        // fh, fc, bh, bc  ([k*32+b])
__device__ float g_hcat[B_ * 1024];
__device__ float g_ccat[B_ * 1024];
__device__ unsigned g_bars[2];

__device__ __forceinline__ float ldcg1(const float* p) {
    float v; asm volatile("ld.global.cg.f32 %0, [%1];" : "=f"(v) : "l"(p)); return v;
}
__device__ __forceinline__ void stcg1(float* p, float v) {
    asm volatile("st.global.cg.f32 [%0], %1;" :: "l"(p), "f"(v));
}
__device__ __forceinline__ unsigned ld_acq(const unsigned* p) {
    unsigned v; asm volatile("ld.acquire.gpu.global.u32 %0, [%1];" : "=r"(v) : "l"(p) : "memory"); return v;
}
__device__ __forceinline__ void red_rel(unsigned* p, unsigned v) {
    asm volatile("red.release.gpu.global.add.u32 [%0], %1;" :: "l"(p), "r"(v) : "memory");
}

// Accurate sigmoid/tanh, immune to --use_fast_math's tanh.approx (whose
// absolute error floor ~5e-4 is ~5% RELATIVE on this network's tiny args).
__device__ __forceinline__ float sigm(float x) {
    return 1.0f / (1.0f + __expf(-x));
}
__device__ __forceinline__ float tanh_acc(float x) {
    float ax = fabsf(x);
    if (ax < 0.4f) {
        float x2 = x * x;
        float p = fmaf(x2, 0.02186949f, -0.05396825f);
        p = fmaf(x2, p, 0.13333334f);
        p = fmaf(x2, p, -0.33333334f);
        return fmaf(x * x2, p, x);
    } else {
        float t = __expf(2.0f * ax);
        float r = 1.0f - 2.0f / (t + 1.0f);
        return copysignf(r, x);
    }
}

// ----------------------------- init ------------------------------------------
__global__ void init_states_kernel() {
    int i = blockIdx.x * blockDim.x + threadIdx.x;
    if (i < 4 * U_ * B_) ((float*)g_S)[i] = 0.0f;
}
__global__ void zero_bars_kernel() {
    if (threadIdx.x < 2) g_bars[threadIdx.x] = 0u;
}

// ----------------------------- mask ------------------------------------------
__global__ void mask_kernel(const float* __restrict__ audio, float* __restrict__ om) {
    int idx = blockIdx.x * blockDim.x + threadIdx.x;
    if (idx >= MT_) return;
    int b = idx / TT_, tc = idx % TT_;
    const float* p = audio + ((size_t)b * 3200 + 4 * (size_t)tc) * 80;
    bool any = false;
    for (int i = 0; i < 320 && !any; i += 4) {
        float4 v = *(const float4*)&p[i];
        any = (v.x != 0.f) | (v.y != 0.f) | (v.z != 0.f) | (v.w != 0.f);
    }
    float m = any ? 1.0f : 0.0f;
    g_mask[idx] = m;
    if (om) om[idx] = m;
}

// ----------------------------- conv1 -----------------------------------------
__global__ __launch_bounds__(256) void conv1_kernel(
    const float* __restrict__ x, const float* __restrict__ w,
    const float* __restrict__ bias)
{
    __shared__ float ws[288];
    __shared__ float bs[32];
    for (int i = threadIdx.x; i < 288; i += 256) ws[i] = w[i];
    if (threadIdx.x < 32) bs[threadIdx.x] = bias[threadIdx.x];
    __syncthreads();
    int idx = blockIdx.x * 256 + threadIdx.x;
    if (idx >= B_ * T1_ * W1_) return;
    int j = idx % W1_; int t = idx / W1_;
    int i = t % T1_;   int b = t / T1_;
    float acc[32];
#pragma unroll
    for (int c = 0; c < 32; ++c) acc[c] = bs[c];
    const float* xb = x + ((size_t)b * 3200 + 2 * (size_t)i) * 80 + 2 * j;
#pragma unroll
    for (int di = 0; di < 3; ++di)
#pragma unroll
        for (int dj = 0; dj < 3; ++dj) {
            float xv = xb[di * 80 + dj];
            const float* wp = &ws[(di * 3 + dj) * 32];
#pragma unroll
            for (int c = 0; c < 32; ++c) acc[c] += xv * wp[c];
        }
    float* yp = g_x1 + (size_t)idx * 32;
#pragma unroll
    for (int c = 0; c < 32; c += 4)
        *(float4*)&yp[c] = make_float4(acc[c], acc[c+1], acc[c+2], acc[c+3]);
}

// ----------------------------- conv2 -----------------------------------------
__global__ __launch_bounds__(256) void conv2_kernel(
    const float* __restrict__ w, const float* __restrict__ bias)
{
    __shared__ float ws[9216];
    __shared__ float bs[32];
    for (int i = threadIdx.x; i < 9216; i += 256) ws[i] = w[i];
    if (threadIdx.x < 32) bs[threadIdx.x] = bias[threadIdx.x];
    __syncthreads();
    int idx = blockIdx.x * 256 + threadIdx.x;
    if (idx >= B_ * TT_ * W2_) return;
    int j = idx % W2_; int t = idx / W2_;
    int i = t % TT_;   int b = t / TT_;
    float acc[32];
#pragma unroll
    for (int c = 0; c < 32; ++c) acc[c] = bs[c];
#pragma unroll
    for (int di = 0; di < 3; ++di)
#pragma unroll
        for (int dj = 0; dj < 3; ++dj) {
            const float* xp = g_x1 + (((size_t)b * T1_ + (2*i+di)) * W1_ + (2*j+dj)) * 32;
            const float* wb = &ws[(di * 3 + dj) * 1024];
            for (int ci = 0; ci < 32; ci += 4) {
                float4 xv = *(const float4*)&xp[ci];
                const float* w0 = &wb[(ci+0)*32];
                const float* w1 = &wb[(ci+1)*32];
                const float* w2 = &wb[(ci+2)*32];
                const float* w3 = &wb[(ci+3)*32];
#pragma unroll
                for (int c = 0; c < 32; ++c)
                    acc[c] += xv.x*w0[c] + xv.y*w1[c] + xv.z*w2[c] + xv.w*w3[c];
            }
        }
    float* yp = g_x2 + (size_t)idx * 32;
#pragma unroll
    for (int c = 0; c < 32; c += 4)
        *(float4*)&yp[c] = make_float4(acc[c], acc[c+1], acc[c+2], acc[c+3]);
}

// ----------------------------- SGEMM -----------------------------------------
// C[M,N] = A[M,K] @ B[K,N] + bias ; mode 1 adds BN + ReLU. N%128==0, K%16==0.
__global__ __launch_bounds__(256) void sgemm_kernel(
    const float* __restrict__ A, const float* __restrict__ Bm,
    const float* __restrict__ bias, float* __restrict__ C,
    int M, int N, int K, int mode,
    const float* __restrict__ gam, const float* __restrict__ bet,
    const float* __restrict__ mu,  const float* __restrict__ var)
{
    __shared__ float As[16][128];
    __shared__ float Bs[16][132];
    const int tid = threadIdx.x;
    const int row0 = blockIdx.y * 128;
    const int col0 = blockIdx.x * 128;
    const int a_m = tid >> 1, a_k = (tid & 1) * 8;
    const int b_k = tid >> 4, b_n = (tid & 15) * 8;
    const int tx = tid & 15, ty = tid >> 4;
    float acc[8][8];
#pragma unroll
    for (int i = 0; i < 8; ++i)
#pragma unroll
        for (int j = 0; j < 8; ++j) acc[i][j] = 0.0f;

    const int nk = K >> 4;
    for (int kt = 0; kt < nk; ++kt) {
        const int k0 = kt << 4;
        {
            int row = row0 + a_m;
            float4 v0 = make_float4(0,0,0,0), v1 = v0;
            if (row < M) {
                const float* ap = A + (size_t)row * K + k0 + a_k;
                v0 = *(const float4*)ap;
                v1 = *(const float4*)(ap + 4);
            }
            As[a_k+0][a_m]=v0.x; As[a_k+1][a_m]=v0.y; As[a_k+2][a_m]=v0.z; As[a_k+3][a_m]=v0.w;
            As[a_k+4][a_m]=v1.x; As[a_k+5][a_m]=v1.y; As[a_k+6][a_m]=v1.z; As[a_k+7][a_m]=v1.w;
        }
        {
            const float* bp = Bm + (size_t)(k0 + b_k) * N + col0 + b_n;
            float4 u0 = *(const float4*)bp;
            float4 u1 = *(const float4*)(bp + 4);
            *(float4*)&Bs[b_k][b_n] = u0;
            *(float4*)&Bs[b_k][b_n+4] = u1;
        }
        __syncthreads();
#pragma unroll
        for (int k = 0; k < 16; ++k) {
            float a[8], b[8];
            *(float4*)&a[0] = *(float4*)&As[k][ty*8];
            *(float4*)&a[4] = *(float4*)&As[k][ty*8+4];
            *(float4*)&b[0] = *(float4*)&Bs[k][tx*8];
            *(float4*)&b[4] = *(float4*)&Bs[k][tx*8+4];
#pragma unroll
            for (int i = 0; i < 8; ++i)
#pragma unroll
                for (int j = 0; j < 8; ++j) acc[i][j] += a[i] * b[j];
        }
        __syncthreads();
    }
    const int cb = col0 + tx * 8;
    float bv[8], sc[8], sh[8];
#pragma unroll
    for (int j = 0; j < 8; ++j) bv[j] = bias[cb + j];
    if (mode == 1) {
#pragma unroll
        for (int j = 0; j < 8; ++j) {
            float a = gam[cb+j] * rsqrtf(var[cb+j] + 1e-3f);
            sc[j] = a;
            sh[j] = bet[cb+j] - mu[cb+j] * a;
        }
    }
#pragma unroll
    for (int i = 0; i < 8; ++i) {
        int row = row0 + ty * 8 + i;
        if (row >= M) break;
        float* cp = C + (size_t)row * N + cb;
        float o[8];
#pragma unroll
        for (int j = 0; j < 8; ++j) {
            float v = acc[i][j] + bv[j];
            if (mode == 1) v = fmaxf(fmaf(v, sc[j], sh[j]), 0.0f);
            o[j] = v;
        }
        *(float4*)&cp[0] = make_float4(o[0], o[1], o[2], o[3]);
        *(float4*)&cp[4] = make_float4(o[4], o[5], o[6], o[7]);
    }
}

// ----------------------------- persistent LSTM layer -------------------------
// 128 blocks x 256 threads: blocks [0,64) fwd, [64,128) bwd; 8 hidden units
// per block. Recurrent weight slice in SMEM; h ping-pongs via L2 + counter
// barrier per step per direction (cg::grid_sync-equivalent release/acquire).
#define LSTM_SMEM ((16384 + 16384 + 1024 + 256 + 256) * 4)

__global__ __launch_bounds__(256) void lstm_layer_kernel(
    const float* __restrict__ frk, const float* __restrict__ brk)
{
    extern __shared__ float sm[];
    float* w_s = sm;                 // [512][32]  col = gate*8 + ul
    float* h_s = sm + 16384;         // [512][32]  [k][b]
    float* z_s = sm + 32768;         // [32][32]   [b][col]
    float* c_s = sm + 33792;         // [32*8]     tid
    float* o_s = sm + 34048;         // [32*8]

    const int tid = threadIdx.x;
    const int dir = blockIdx.x >> 6;
    const int u0  = (blockIdx.x & 63) * 8;
    const float* rk = dir ? brk : frk;
    const float* z  = dir ? g_zb : g_zf;
    float* Sh = g_S[dir * 2 + 0];
    float* Sc = g_S[dir * 2 + 1];

    for (int idx = tid; idx < 16384; idx += 256) {
        int k = idx >> 5, c = idx & 31;
        w_s[idx] = rk[(size_t)k * G4_ + (size_t)(c >> 3) * U_ + u0 + (c & 7)];
    }
    {
        int b = tid >> 3, ul = tid & 7;
        c_s[tid] = ldcg1(&Sc[(u0 + ul) * 32 + b]);
        o_s[tid] = 0.0f;
    }
    for (int idx = tid * 4; idx < 16384; idx += 1024) {
        float4 v;
        v.x = ldcg1(&Sh[idx]); v.y = ldcg1(&Sh[idx+1]);
        v.z = ldcg1(&Sh[idx+2]); v.w = ldcg1(&Sh[idx+3]);
        *(float4*)&h_s[idx] = v;
    }
    __syncthreads();

    const int mb  = tid >> 3;
    const int c4  = (tid & 7) * 4;
    const int gg_ = c4 >> 3;
    const int ul4 = c4 & 7;

    for (int s = 0; s < TT_; ++s) {
        const int t = dir ? (TT_ - 1 - s) : s;
        float a0 = 0.f, a1 = 0.f, a2 = 0.f, a3 = 0.f;
        const float* hp = h_s + mb;
        const float* wp = w_s + c4;
#pragma unroll 8
        for (int k = 0; k < 512; ++k) {
            float hv = hp[k << 5];
            float4 w = *(const float4*)&wp[k << 5];
            a0 += hv * w.x; a1 += hv * w.y; a2 += hv * w.z; a3 += hv * w.w;
        }
        {
            const float4 zv = *(const float4*)(z + ((size_t)mb * TT_ + t) * G4_
                                               + (size_t)gg_ * U_ + u0 + ul4);
            a0 += zv.x; a1 += zv.y; a2 += zv.z; a3 += zv.w;
        }
        *(float4*)&z_s[(mb << 5) + c4] = make_float4(a0, a1, a2, a3);
        __syncthreads();

        {
            int b = tid >> 3, ul = tid & 7;
            float zi = z_s[(b << 5) + ul];
            float zf = z_s[(b << 5) + 8 + ul];
            float zg = z_s[(b << 5) + 16 + ul];
            float zo = z_s[(b << 5) + 24 + ul];
            float ig = sigm(zi), fg = sigm(zf);
            float gv = tanh_acc(zg), og = sigm(zo);
            float cold = c_s[tid];
            float cn = fg * cold + ig * gv;
            float hn = og * tanh_acc(cn);
            bool m = (g_mask[b * TT_ + t] != 0.0f);
            float hold = h_s[((u0 + ul) << 5) + b];
            float hsel = m ? hn : hold;
            float csel = m ? cn : cold;
            float osel = m ? hn : o_s[tid];
            c_s[tid] = csel;
            o_s[tid] = osel;
            g_xcat[((size_t)b * TT_ + t) * 1024 + (size_t)dir * U_ + u0 + ul] = osel;
            stcg1(&g_H[dir][s & 1][((u0 + ul) << 5) + b], hsel);
            if (s == TT_ - 1) {
                Sh[((u0 + ul) << 5) + b] = hsel;
                Sc[((u0 + ul) << 5) + b] = csel;
            }
        }
        // ---- release: every thread fences its own stores, then block arrives
        __threadfence();
        __syncthreads();
        if (tid == 0) {
            red_rel(&g_bars[dir], 1u);
            const unsigned tgt = 64u * (unsigned)(s + 1);
            while (ld_acq(&g_bars[dir]) < tgt) { }
        }
        __syncthreads();
        // ---- acquire side: restage via L2-direct loads
        if (s < TT_ - 1) {
            const float* Hr = g_H[dir][s & 1];
            for (int idx = tid * 4; idx < 16384; idx += 1024) {
                float4 v;
                v.x = ldcg1(&Hr[idx]);   v.y = ldcg1(&Hr[idx+1]);
                v.z = ldcg1(&Hr[idx+2]); v.w = ldcg1(&Hr[idx+3]);
                *(float4*)&h_s[idx] = v;
            }
            __syncthreads();
        }
    }
}

// ----------------------------- h/c concat ------------------------------------
__global__ void hcat_kernel() {
    int idx = blockIdx.x * blockDim.x + threadIdx.x;
    if (idx >= B_ * 1024) return;
    int b = idx >> 10, u = idx & 1023;
    float hv, cv;
    if (u < U_) { hv = g_S[0][u * 32 + b];        cv = g_S[1][u * 32 + b]; }
    else        { hv = g_S[2][(u - U_) * 32 + b]; cv = g_S[3][(u - U_) * 32 + b]; }
    g_hcat[idx] = hv;
    g_ccat[idx] = cv;
}

// ----------------------------- launch ----------------------------------------
extern "C" void kernel_launch(void* const* d_in, const int* in_sizes, int n_in,
                              void* d_out, int out_size)
{
    const float* audio = (const float*)d_in[0];
    const float* c1w = (const float*)d_in[1];
    const float* c1b = (const float*)d_in[2];
    const float* c2w = (const float*)d_in[3];
    const float* c2b = (const float*)d_in[4];
    const float* fk0 = (const float*)d_in[5];
    const float* bk0 = (const float*)d_in[6];
    const float* fk  = (const float*)d_in[7];
    const float* bk  = (const float*)d_in[8];
    const float* frec = (const float*)d_in[9];
    const float* brec = (const float*)d_in[10];
    const float* fb  = (const float*)d_in[11];
    const float* bb  = (const float*)d_in[12];
    const float* pw  = (const float*)d_in[13];
    const float* pb  = (const float*)d_in[14];
    const float* bng = (const float*)d_in[15];
    const float* bnb = (const float*)d_in[16];
    const float* bnm = (const float*)d_in[17];
    const float* bnv = (const float*)d_in[18];
    const float* hpw = (const float*)d_in[19];
    const float* hpb = (const float*)d_in[20];
    const float* cpw = (const float*)d_in[21];
    const float* cpb = (const float*)d_in[22];
    float* out = (float*)d_out;

    void* p;
    float *x2, *zf, *zb, *xcat, *xp0, *xp1, *hcat, *ccat;
    cudaGetSymbolAddress(&p, g_x2);   x2 = (float*)p;
    cudaGetSymbolAddress(&p, g_zf);   zf = (float*)p;
    cudaGetSymbolAddress(&p, g_zb);   zb = (float*)p;
    cudaGetSymbolAddress(&p, g_xcat); xcat = (float*)p;
    cudaGetSymbolAddress(&p, g_xp0);  xp0 = (float*)p;
    cudaGetSymbolAddress(&p, g_xp1);  xp1 = (float*)p;
    cudaGetSymbolAddress(&p, g_hcat); hcat = (float*)p;
    cudaGetSymbolAddress(&p, g_ccat); ccat = (float*)p;

    cudaFuncSetAttribute(lstm_layer_kernel,
                         cudaFuncAttributeMaxDynamicSharedMemorySize, LSTM_SMEM);

    const bool wantMask = ((size_t)out_size >= OFF_M + MT_);
    const bool wantHC   = ((size_t)out_size >= TOTAL_);

    init_states_kernel<<<(4 * U_ * B_ + 255) / 256, 256>>>();
    mask_kernel<<<(MT_ + 255) / 256, 256>>>(audio, wantMask ? (out + OFF_M) : nullptr);
    conv1_kernel<<<(B_ * T1_ * W1_ + 255) / 256, 256>>>(audio, c1w, c1b);
    conv2_kernel<<<(B_ * TT_ * W2_ + 255) / 256, 256>>>(c2w, c2b);

    const float* xin = x2;
    int Din = D0_;
    for (int i = 0; i < 3; ++i) {
        const float* fki = (i == 0) ? fk0 : fk + (size_t)(i - 1) * 1024 * G4_;
        const float* bki = (i == 0) ? bk0 : bk + (size_t)(i - 1) * 1024 * G4_;
        dim3 gz(G4_ / 128, (MT_ + 127) / 128);
        sgemm_kernel<<<gz, 256>>>(xin, fki, fb + (size_t)i * G4_, zf,
                                  MT_, G4_, Din, 0, nullptr, nullptr, nullptr, nullptr);
        sgemm_kernel<<<gz, 256>>>(xin, bki, bb + (size_t)i * G4_, zb,
                                  MT_, G4_, Din, 0, nullptr, nullptr, nullptr, nullptr);

        zero_bars_kernel<<<1, 32>>>();
        lstm_layer_kernel<<<128, 256, LSTM_SMEM>>>(
            frec + (size_t)i * U_ * G4_, brec + (size_t)i * U_ * G4_);

        float* dst = (i == 0) ? xp0 : (i == 1) ? xp1 : out;
        dim3 gp(1024 / 128, (MT_ + 127) / 128);
        sgemm_kernel<<<gp, 256>>>(xcat, pw + (size_t)i * 1024 * 1024,
                                  pb + (size_t)i * 1024, dst,
                                  MT_, 1024, 1024, 1,
                                  bng + (size_t)i * 1024, bnb + (size_t)i * 1024,
                                  bnm + (size_t)i * 1024, bnv + (size_t)i * 1024);
        xin = dst;
        Din = 1024;
    }

    if (wantHC) {
        hcat_kernel<<<(B_ * 1024 + 255) / 256, 256>>>();
        dim3 gh(512 / 128, 1);
        sgemm_kernel<<<gh, 256>>>(hcat, hpw, hpb, out + OFF_H,
                                  B_, 512, 1024, 0, nullptr, nullptr, nullptr, nullptr);
        sgemm_kernel<<<gh, 256>>>(ccat, cpw, cpb, out + OFF_C,
                                  B_, 512, 1024, 0, nullptr, nullptr, nullptr, nullptr);
    }
}

// round 6
// speedup vs baseline: 1.0003x; 1.0003x over previous
#include <cuda_runtime.h>
#include <cuda_bf16.h>
#include <math.h>
#include <stdint.h>

#define B_   32
#define TT_  799
#define T1_  1599
#define W1_  39
#define W2_  19
#define D0_  608
#define U_   512
#define G4_  2048
#define MT_  (B_ * TT_)            // 25568

#define X_SZ   ((size_t)MT_ * 1024)
#define OFF_M  (X_SZ)
#define OFF_H  (X_SZ + MT_)
#define OFF_C  (OFF_H + (size_t)B_ * 512)
#define TOTAL_ (OFF_C + (size_t)B_ * 512)

// ----------------------------- scratch --------------------------------------
__device__ float g_x1[(size_t)B_ * T1_ * W1_ * 32];
__device__ float g_x2[(size_t)MT_ * D0_];
__device__ float g_zf[(size_t)MT_ * G4_];
__device__ float g_zb[(size_t)MT_ * G4_];
__device__ float g_xcat[(size_t)MT_ * 1024];
__device__ float g_xp0[(size_t)MT_ * 1024];
__device__ float g_xp1[(size_t)MT_ * 1024];
__device__ float g_mask[MT_];
__device__ float g_H[2][2][U_ * B_];     // [dir][parity][k*32+b]
__device__ float g_S[4][U_ * B_];        // fh, fc, bh, bc  ([k*32+b])
__device__ float g_hcat[B_ * 1024];
__device__ float g_ccat[B_ * 1024];
__device__ unsigned g_bars[2];

__device__ __forceinline__ float ldcg1(const float* p) {
    float v; asm volatile("ld.global.cg.f32 %0, [%1];" : "=f"(v) : "l"(p)); return v;
}
__device__ __forceinline__ void stcg1(float* p, float v) {
    asm volatile("st.global.cg.f32 [%0], %1;" :: "l"(p), "f"(v));
}
__device__ __forceinline__ unsigned ld_acq(const unsigned* p) {
    unsigned v; asm volatile("ld.acquire.gpu.global.u32 %0, [%1];" : "=r"(v) : "l"(p) : "memory"); return v;
}
__device__ __forceinline__ void red_rel(unsigned* p, unsigned v) {
    asm volatile("red.release.gpu.global.add.u32 [%0], %1;" :: "l"(p), "r"(v) : "memory");
}

// Accurate sigmoid/tanh, immune to --use_fast_math's tanh.approx (whose
// absolute error floor ~5e-4 is ~5% RELATIVE on this network's tiny args).
__device__ __forceinline__ float sigm(float x) {
    return 1.0f / (1.0f + __expf(-x));
}
__device__ __forceinline__ float tanh_acc(float x) {
    float ax = fabsf(x);
    if (ax < 0.4f) {
        float x2 = x * x;
        float p = fmaf(x2, 0.02186949f, -0.05396825f);
        p = fmaf(x2, p, 0.13333334f);
        p = fmaf(x2, p, -0.33333334f);
        return fmaf(x * x2, p, x);
    } else {
        float t = __expf(2.0f * ax);
        float r = 1.0f - 2.0f / (t + 1.0f);
        return copysignf(r, x);
    }
}

// ----------------------------- init ------------------------------------------
__global__ void init_states_kernel() {
    int i = blockIdx.x * blockDim.x + threadIdx.x;
    if (i < 4 * U_ * B_) ((float*)g_S)[i] = 0.0f;
}
__global__ void zero_bars_kernel() {
    if (threadIdx.x < 2) g_bars[threadIdx.x] = 0u;
}

// ----------------------------- mask ------------------------------------------
__global__ void mask_kernel(const float* __restrict__ audio, float* __restrict__ om) {
    int idx = blockIdx.x * blockDim.x + threadIdx.x;
    if (idx >= MT_) return;
    int b = idx / TT_, tc = idx % TT_;
    const float* p = audio + ((size_t)b * 3200 + 4 * (size_t)tc) * 80;
    bool any = false;
    for (int i = 0; i < 320 && !any; i += 4) {
        float4 v = *(const float4*)&p[i];
        any = (v.x != 0.f) | (v.y != 0.f) | (v.z != 0.f) | (v.w != 0.f);
    }
    float m = any ? 1.0f : 0.0f;
    g_mask[idx] = m;
    if (om) om[idx] = m;
}

// ----------------------------- conv1 -----------------------------------------
__global__ __launch_bounds__(256) void conv1_kernel(
    const float* __restrict__ x, const float* __restrict__ w,
    const float* __restrict__ bias)
{
    __shared__ float ws[288];
    __shared__ float bs[32];
    for (int i = threadIdx.x; i < 288; i += 256) ws[i] = w[i];
    if (threadIdx.x < 32) bs[threadIdx.x] = bias[threadIdx.x];
    __syncthreads();
    int idx = blockIdx.x * 256 + threadIdx.x;
    if (idx >= B_ * T1_ * W1_) return;
    int j = idx % W1_; int t = idx / W1_;
    int i = t % T1_;   int b = t / T1_;
    float acc[32];
#pragma unroll
    for (int c = 0; c < 32; ++c) acc[c] = bs[c];
    const float* xb = x + ((size_t)b * 3200 + 2 * (size_t)i) * 80 + 2 * j;
#pragma unroll
    for (int di = 0; di < 3; ++di)
#pragma unroll
        for (int dj = 0; dj < 3; ++dj) {
            float xv = xb[di * 80 + dj];
            const float* wp = &ws[(di * 3 + dj) * 32];
#pragma unroll
            for (int c = 0; c < 32; ++c) acc[c] += xv * wp[c];
        }
    float* yp = g_x1 + (size_t)idx * 32;
#pragma unroll
    for (int c = 0; c < 32; c += 4)
        *(float4*)&yp[c] = make_float4(acc[c], acc[c+1], acc[c+2], acc[c+3]);
}

// ----------------------------- conv2 -----------------------------------------
__global__ __launch_bounds__(256) void conv2_kernel(
    const float* __restrict__ w, const float* __restrict__ bias)
{
    __shared__ float ws[9216];
    __shared__ float bs[32];
    for (int i = threadIdx.x; i < 9216; i += 256) ws[i] = w[i];
    if (threadIdx.x < 32) bs[threadIdx.x] = bias[threadIdx.x];
    __syncthreads();
    int idx = blockIdx.x * 256 + threadIdx.x;
    if (idx >= B_ * TT_ * W2_) return;
    int j = idx % W2_; int t = idx / W2_;
    int i = t % TT_;   int b = t / TT_;
    float acc[32];
#pragma unroll
    for (int c = 0; c < 32; ++c) acc[c] = bs[c];
#pragma unroll
    for (int di = 0; di < 3; ++di)
#pragma unroll
        for (int dj = 0; dj < 3; ++dj) {
            const float* xp = g_x1 + (((size_t)b * T1_ + (2*i+di)) * W1_ + (2*j+dj)) * 32;
            const float* wb = &ws[(di * 3 + dj) * 1024];
            for (int ci = 0; ci < 32; ci += 4) {
                float4 xv = *(const float4*)&xp[ci];
                const float* w0 = &wb[(ci+0)*32];
                const float* w1 = &wb[(ci+1)*32];
                const float* w2 = &wb[(ci+2)*32];
                const float* w3 = &wb[(ci+3)*32];
#pragma unroll
                for (int c = 0; c < 32; ++c)
                    acc[c] += xv.x*w0[c] + xv.y*w1[c] + xv.z*w2[c] + xv.w*w3[c];
            }
        }
    float* yp = g_x2 + (size_t)idx * 32;
#pragma unroll
    for (int c = 0; c < 32; c += 4)
        *(float4*)&yp[c] = make_float4(acc[c], acc[c+1], acc[c+2], acc[c+3]);
}

// ----------------------------- SGEMM -----------------------------------------
// C[M,N] = A[M,K] @ B[K,N] + bias ; mode 1 adds BN + ReLU. N%128==0, K%16==0.
__global__ __launch_bounds__(256) void sgemm_kernel(
    const float* __restrict__ A, const float* __restrict__ Bm,
    const float* __restrict__ bias, float* __restrict__ C,
    int M, int N, int K, int mode,
    const float* __restrict__ gam, const float* __restrict__ bet,
    const float* __restrict__ mu,  const float* __restrict__ var)
{
    __shared__ float As[16][128];
    __shared__ float Bs[16][132];
    const int tid = threadIdx.x;
    const int row0 = blockIdx.y * 128;
    const int col0 = blockIdx.x * 128;
    const int a_m = tid >> 1, a_k = (tid & 1) * 8;
    const int b_k = tid >> 4, b_n = (tid & 15) * 8;
    const int tx = tid & 15, ty = tid >> 4;
    float acc[8][8];
#pragma unroll
    for (int i = 0; i < 8; ++i)
#pragma unroll
        for (int j = 0; j < 8; ++j) acc[i][j] = 0.0f;

    const int nk = K >> 4;
    for (int kt = 0; kt < nk; ++kt) {
        const int k0 = kt << 4;
        {
            int row = row0 + a_m;
            float4 v0 = make_float4(0,0,0,0), v1 = v0;
            if (row < M) {
                const float* ap = A + (size_t)row * K + k0 + a_k;
                v0 = *(const float4*)ap;
                v1 = *(const float4*)(ap + 4);
            }
            As[a_k+0][a_m]=v0.x; As[a_k+1][a_m]=v0.y; As[a_k+2][a_m]=v0.z; As[a_k+3][a_m]=v0.w;
            As[a_k+4][a_m]=v1.x; As[a_k+5][a_m]=v1.y; As[a_k+6][a_m]=v1.z; As[a_k+7][a_m]=v1.w;
        }
        {
            const float* bp = Bm + (size_t)(k0 + b_k) * N + col0 + b_n;
            float4 u0 = *(const float4*)bp;
            float4 u1 = *(const float4*)(bp + 4);
            *(float4*)&Bs[b_k][b_n] = u0;
            *(float4*)&Bs[b_k][b_n+4] = u1;
        }
        __syncthreads();
#pragma unroll
        for (int k = 0; k < 16; ++k) {
            float a[8], b[8];
            *(float4*)&a[0] = *(float4*)&As[k][ty*8];
            *(float4*)&a[4] = *(float4*)&As[k][ty*8+4];
            *(float4*)&b[0] = *(float4*)&Bs[k][tx*8];
            *(float4*)&b[4] = *(float4*)&Bs[k][tx*8+4];
#pragma unroll
            for (int i = 0; i < 8; ++i)
#pragma unroll
                for (int j = 0; j < 8; ++j) acc[i][j] += a[i] * b[j];
        }
        __syncthreads();
    }
    const int cb = col0 + tx * 8;
    float bv[8], sc[8], sh[8];
#pragma unroll
    for (int j = 0; j < 8; ++j) bv[j] = bias[cb + j];
    if (mode == 1) {
#pragma unroll
        for (int j = 0; j < 8; ++j) {
            float a = gam[cb+j] * rsqrtf(var[cb+j] + 1e-3f);
            sc[j] = a;
            sh[j] = bet[cb+j] - mu[cb+j] * a;
        }
    }
#pragma unroll
    for (int i = 0; i < 8; ++i) {
        int row = row0 + ty * 8 + i;
        if (row >= M) break;
        float* cp = C + (size_t)row * N + cb;
        float o[8];
#pragma unroll
        for (int j = 0; j < 8; ++j) {
            float v = acc[i][j] + bv[j];
            if (mode == 1) v = fmaxf(fmaf(v, sc[j], sh[j]), 0.0f);
            o[j] = v;
        }
        *(float4*)&cp[0] = make_float4(o[0], o[1], o[2], o[3]);
        *(float4*)&cp[4] = make_float4(o[4], o[5], o[6], o[7]);
    }
}

// ----------------------------- persistent LSTM layer -------------------------
// 128 blocks x 256 threads: blocks [0,64) fwd, [64,128) bwd; 8 hidden units
// per block. Recurrent weight slice in SMEM; h ping-pongs via L2 + counter
// barrier per step per direction (cg::grid_sync-equivalent release/acquire).
#define LSTM_SMEM ((16384 + 16384 + 1024 + 256 + 256) * 4)

__global__ __launch_bounds__(256) void lstm_layer_kernel(
    const float* __restrict__ frk, const float* __restrict__ brk)
{
    extern __shared__ float sm[];
    float* w_s = sm;                 // [512][32]  col = gate*8 + ul
    float* h_s = sm + 16384;         // [512][32]  [k][b]
    float* z_s = sm + 32768;         // [32][32]   [b][col]
    float* c_s = sm + 33792;         // [32*8]     tid
    float* o_s = sm + 34048;         // [32*8]

    const int tid = threadIdx.x;
    const int dir = blockIdx.x >> 6;
    const int u0  = (blockIdx.x & 63) * 8;
    const float* rk = dir ? brk : frk;
    const float* z  = dir ? g_zb : g_zf;
    float* Sh = g_S[dir * 2 + 0];
    float* Sc = g_S[dir * 2 + 1];

    for (int idx = tid; idx < 16384; idx += 256) {
        int k = idx >> 5, c = idx & 31;
        w_s[idx] = rk[(size_t)k * G4_ + (size_t)(c >> 3) * U_ + u0 + (c & 7)];
    }
    {
        int b = tid >> 3, ul = tid & 7;
        c_s[tid] = ldcg1(&Sc[(u0 + ul) * 32 + b]);
        o_s[tid] = 0.0f;
    }
    for (int idx = tid * 4; idx < 16384; idx += 1024) {
        float4 v;
        v.x = ldcg1(&Sh[idx]); v.y = ldcg1(&Sh[idx+1]);
        v.z = ldcg1(&Sh[idx+2]); v.w = ldcg1(&Sh[idx+3]);
        *(float4*)&h_s[idx] = v;
    }
    __syncthreads();

    const int mb  = tid >> 3;
    const int c4  = (tid & 7) * 4;
    const int gg_ = c4 >> 3;
    const int ul4 = c4 & 7;

    for (int s = 0; s < TT_; ++s) {
        const int t = dir ? (TT_ - 1 - s) : s;
        float a0 = 0.f, a1 = 0.f, a2 = 0.f, a3 = 0.f;
        const float* hp = h_s + mb;
        const float* wp = w_s + c4;
#pragma unroll 8
        for (int k = 0; k < 512; ++k) {
            float hv = hp[k << 5];
            float4 w = *(const float4*)&wp[k << 5];
            a0 += hv * w.x; a1 += hv * w.y; a2 += hv * w.z; a3 += hv * w.w;
        }
        {
            const float4 zv = *(const float4*)(z + ((size_t)mb * TT_ + t) * G4_
                                               + (size_t)gg_ * U_ + u0 + ul4);
            a0 += zv.x; a1 += zv.y; a2 += zv.z; a3 += zv.w;
        }
        *(float4*)&z_s[(mb << 5) + c4] = make_float4(a0, a1, a2, a3);
        __syncthreads();

        {
            int b = tid >> 3, ul = tid & 7;
            float zi = z_s[(b << 5) + ul];
            float zf = z_s[(b << 5) + 8 + ul];
            float zg = z_s[(b << 5) + 16 + ul];
            float zo = z_s[(b << 5) + 24 + ul];
            float ig = sigm(zi), fg = sigm(zf);
            float gv = tanh_acc(zg), og = sigm(zo);
            float cold = c_s[tid];
            float cn = fg * cold + ig * gv;
            float hn = og * tanh_acc(cn);
            bool m = (g_mask[b * TT_ + t] != 0.0f);
            float hold = h_s[((u0 + ul) << 5) + b];
            float hsel = m ? hn : hold;
            float csel = m ? cn : cold;
            float osel = m ? hn : o_s[tid];
            c_s[tid] = csel;
            o_s[tid] = osel;
            g_xcat[((size_t)b * TT_ + t) * 1024 + (size_t)dir * U_ + u0 + ul] = osel;
            stcg1(&g_H[dir][s & 1][((u0 + ul) << 5) + b], hsel);
            if (s == TT_ - 1) {
                Sh[((u0 + ul) << 5) + b] = hsel;
                Sc[((u0 + ul) << 5) + b] = csel;
            }
        }
        // ---- release: every thread fences its own stores, then block arrives
        __threadfence();
        __syncthreads();
        if (tid == 0) {
            red_rel(&g_bars[dir], 1u);
            const unsigned tgt = 64u * (unsigned)(s + 1);
            while (ld_acq(&g_bars[dir]) < tgt) { }
        }
        __syncthreads();
        // ---- acquire side: restage via L2-direct loads
        if (s < TT_ - 1) {
            const float* Hr = g_H[dir][s & 1];
            for (int idx = tid * 4; idx < 16384; idx += 1024) {
                float4 v;
                v.x = ldcg1(&Hr[idx]);   v.y = ldcg1(&Hr[idx+1]);
                v.z = ldcg1(&Hr[idx+2]); v.w = ldcg1(&Hr[idx+3]);
                *(float4*)&h_s[idx] = v;
            }
            __syncthreads();
        }
    }
}

// ----------------------------- h/c concat ------------------------------------
__global__ void hcat_kernel() {
    int idx = blockIdx.x * blockDim.x + threadIdx.x;
    if (idx >= B_ * 1024) return;
    int b = idx >> 10, u = idx & 1023;
    float hv, cv;
    if (u < U_) { hv = g_S[0][u * 32 + b];        cv = g_S[1][u * 32 + b]; }
    else        { hv = g_S[2][(u - U_) * 32 + b]; cv = g_S[3][(u - U_) * 32 + b]; }
    g_hcat[idx] = hv;
    g_ccat[idx] = cv;
}

// ----------------------------- launch ----------------------------------------
extern "C" void kernel_launch(void* const* d_in, const int* in_sizes, int n_in,
                              void* d_out, int out_size)
{
    const float* audio = (const float*)d_in[0];
    const float* c1w = (const float*)d_in[1];
    const float* c1b = (const float*)d_in[2];
    const float* c2w = (const float*)d_in[3];
    const float* c2b = (const float*)d_in[4];
    const float* fk0 = (const float*)d_in[5];
    const float* bk0 = (const float*)d_in[6];
    const float* fk  = (const float*)d_in[7];
    const float* bk  = (const float*)d_in[8];
    const float* frec = (const float*)d_in[9];
    const float* brec = (const float*)d_in[10];
    const float* fb  = (const float*)d_in[11];
    const float* bb  = (const float*)d_in[12];
    const float* pw  = (const float*)d_in[13];
    const float* pb  = (const float*)d_in[14];
    const float* bng = (const float*)d_in[15];
    const float* bnb = (const float*)d_in[16];
    const float* bnm = (const float*)d_in[17];
    const float* bnv = (const float*)d_in[18];
    const float* hpw = (const float*)d_in[19];
    const float* hpb = (const float*)d_in[20];
    const float* cpw = (const float*)d_in[21];
    const float* cpb = (const float*)d_in[22];
    float* out = (float*)d_out;

    void* p;
    float *x2, *zf, *zb, *xcat, *xp0, *xp1, *hcat, *ccat;
    cudaGetSymbolAddress(&p, g_x2);   x2 = (float*)p;
    cudaGetSymbolAddress(&p, g_zf);   zf = (float*)p;
    cudaGetSymbolAddress(&p, g_zb);   zb = (float*)p;
    cudaGetSymbolAddress(&p, g_xcat); xcat = (float*)p;
    cudaGetSymbolAddress(&p, g_xp0);  xp0 = (float*)p;
    cudaGetSymbolAddress(&p, g_xp1);  xp1 = (float*)p;
    cudaGetSymbolAddress(&p, g_hcat); hcat = (float*)p;
    cudaGetSymbolAddress(&p, g_ccat); ccat = (float*)p;

    cudaFuncSetAttribute(lstm_layer_kernel,
                         cudaFuncAttributeMaxDynamicSharedMemorySize, LSTM_SMEM);

    const bool wantMask = ((size_t)out_size >= OFF_M + MT_);
    const bool wantHC   = ((size_t)out_size >= TOTAL_);

    init_states_kernel<<<(4 * U_ * B_ + 255) / 256, 256>>>();
    mask_kernel<<<(MT_ + 255) / 256, 256>>>(audio, wantMask ? (out + OFF_M) : nullptr);
    conv1_kernel<<<(B_ * T1_ * W1_ + 255) / 256, 256>>>(audio, c1w, c1b);
    conv2_kernel<<<(B_ * TT_ * W2_ + 255) / 256, 256>>>(c2w, c2b);

    const float* xin = x2;
    int Din = D0_;
    for (int i = 0; i < 3; ++i) {
        const float* fki = (i == 0) ? fk0 : fk + (size_t)(i - 1) * 1024 * G4_;
        const float* bki = (i == 0) ? bk0 : bk + (size_t)(i - 1) * 1024 * G4_;
        dim3 gz(G4_ / 128, (MT_ + 127) / 128);
        sgemm_kernel<<<gz, 256>>>(xin, fki, fb + (size_t)i * G4_, zf,
                                  MT_, G4_, Din, 0, nullptr, nullptr, nullptr, nullptr);
        sgemm_kernel<<<gz, 256>>>(xin, bki, bb + (size_t)i * G4_, zb,
                                  MT_, G4_, Din, 0, nullptr, nullptr, nullptr, nullptr);

        zero_bars_kernel<<<1, 32>>>();
        lstm_layer_kernel<<<128, 256, LSTM_SMEM>>>(
            frec + (size_t)i * U_ * G4_, brec + (size_t)i * U_ * G4_);

        float* dst = (i == 0) ? xp0 : (i == 1) ? xp1 : out;
        dim3 gp(1024 / 128, (MT_ + 127) / 128);
        sgemm_kernel<<<gp, 256>>>(xcat, pw + (size_t)i * 1024 * 1024,
                                  pb + (size_t)i * 1024, dst,
                                  MT_, 1024, 1024, 1,
                                  bng + (size_t)i * 1024, bnb + (size_t)i * 1024,
                                  bnm + (size_t)i * 1024, bnv + (size_t)i * 1024);
        xin = dst;
        Din = 1024;
    }

    if (wantHC) {
        hcat_kernel<<<(B_ * 1024 + 255) / 256, 256>>>();
        dim3 gh(512 / 128, 1);
        sgemm_kernel<<<gh, 256>>>(hcat, hpw, hpb, out + OFF_H,
                                  B_, 512, 1024, 0, nullptr, nullptr, nullptr, nullptr);
        sgemm_kernel<<<gh, 256>>>(ccat, cpw, cpb, out + OFF_C,
                                  B_, 512, 1024, 0, nullptr, nullptr, nullptr, nullptr);
    }
}